// round 3
// baseline (speedup 1.0000x reference)
#include <cuda_runtime.h>

// CTC loss (scaled forward algorithm, linear domain), warp-specialized.
// B=512, T=512, C=256, L=64, S=129, blank = C-1.
// Per block: 1 batch. Warp 0 = recurrence, warps 1-3 = smem gather producers.
// Rescale is lagged by one 4-step group, so the target is biased to 2^40
// to keep the working range well above FP32 flush-to-zero.

#define TT 512
#define CC 256
#define BB 512
#define LL 64
#define SS 129
#define EPSF 1e-7f
#define CHUNK 32
#define NCH   16            // ceil((T-1)/CHUNK)
#define ROW   68            // floats per t-row: [0..63]=labels, [64]=blank, pad

__global__ __launch_bounds__(128, 4)
void ctc_scaled_kernel(const int* __restrict__ y_true,
                       const float* __restrict__ y_pred,
                       float* __restrict__ out)
{
    __shared__ float sp[2][CHUNK][ROW];
    __shared__ int   slab[LL];

    const int b    = blockIdx.x;
    const int tid  = threadIdx.x;
    const int w    = tid >> 5;
    const int lane = tid & 31;
    const unsigned FULL = 0xFFFFFFFFu;

    const float* __restrict__ yp = y_pred + (size_t)b * TT * CC;

    if (tid < LL) slab[tid] = y_true[b * LL + tid];
    __syncthreads();

    // ---------------- consumer-side static state ----------------
    float a[5];
    int   off[5];
    float skipf[5];
    const int lm1 = (lane + 31) & 31;
    const int lm2 = (lane + 30) & 31;

    // ---------------- producer-side registers ----------------
    int labA = 0, labB = 0;
    if (w > 0) { labA = slab[lane]; labB = slab[lane + 32]; }

    if (w == 0) {
        // state metadata: s = 32k+lane; odd s -> label (s-1)/2, else blank slot 64
#pragma unroll
        for (int k = 0; k < 5; k++) {
            int s = 32 * k + lane;
            if (s < SS && (s & 1)) {
                int idx = (s - 1) >> 1;
                off[k] = idx;
                skipf[k] = (idx > 0 && slab[idx] != slab[idx - 1]) ? 1.0f : 0.0f;
            } else {
                off[k] = 64;        // blank slot (also safe for invalid s>128)
                skipf[k] = 0.0f;
            }
        }
        // t = 0 init: states 0 (blank) and 1 (label 0)
#pragma unroll
        for (int k = 0; k < 5; k++) a[k] = 0.0f;
        if (lane == 0)      a[0] = yp[CC - 1] + EPSF;
        else if (lane == 1) a[0] = yp[slab[0]] + EPSF;
    } else {
        // prologue: fill chunk 0 (t = 1 .. 32) into buf 0
        for (int j = w - 1; j < CHUNK; j += 3) {
            int t = 1 + j;
            const float* row = yp + (size_t)t * CC;
            sp[0][j][lane]      = row[labA] + EPSF;
            sp[0][j][lane + 32] = row[labB] + EPSF;
            if (lane == 0) sp[0][j][64] = row[CC - 1] + EPSF;
        }
    }
    __syncthreads();

    int E = 0;

    for (int c = 0; c < NCH; c++) {
        if (w == 0) {
            // -------- consume chunk c from buf (c&1) --------
            const int buf   = c & 1;
            const int tbase = 1 + c * CHUNK;
            float p[5];
            {
                const float* r0 = &sp[buf][0][0];
#pragma unroll
                for (int k = 0; k < 5; k++) p[k] = r0[off[k]];
            }

#pragma unroll 1
            for (int g = 0; g < CHUNK / 4; g++) {
                // max measured at group start (== end of previous group),
                // butterfly interleaved with the 4 steps, scale applied at
                // group end.  Target biased to 2^40 to absorb the 4-step
                // decay lag while keeping small states above FTZ.
                float m = fmaxf(fmaxf(fmaxf(a[0], a[1]), fmaxf(a[2], a[3])), a[4]);
                m = fmaxf(m, __shfl_xor_sync(FULL, m, 16));

#pragma unroll
                for (int i = 0; i < 4; i++) {
                    int j = g * 4 + i;
                    int t = tbase + j;
                    if (t < TT) {
                        bool pf = (j + 1 < CHUNK) && (t + 1 < TT);
                        float np[5];
                        const float* rn = &sp[buf][j + 1][0];
                        if (pf) {
#pragma unroll
                            for (int k = 0; k < 5; k++) np[k] = rn[off[k]];
                        }
                        float r1[5], r2[5];
#pragma unroll
                        for (int k = 0; k < 5; k++) r1[k] = __shfl_sync(FULL, a[k], lm1);
#pragma unroll
                        for (int k = 0; k < 5; k++) r2[k] = __shfl_sync(FULL, a[k], lm2);
#pragma unroll
                        for (int k = 0; k < 5; k++) {
                            float u1 = r1[k];
                            if (lane == 0) u1 = (k > 0) ? r1[k - 1] : 0.0f;
                            float u2 = r2[k];
                            if (lane < 2)  u2 = (k > 0) ? r2[k - 1] : 0.0f;
                            float sum = a[k] + u1 + skipf[k] * u2;
                            a[k] = sum * p[k];
                            if (pf) p[k] = np[k];
                        }
                    }
                    // interleave one butterfly stage per step
                    if (i == 0) m = fmaxf(m, __shfl_xor_sync(FULL, m, 8));
                    if (i == 1) m = fmaxf(m, __shfl_xor_sync(FULL, m, 4));
                    if (i == 2) m = fmaxf(m, __shfl_xor_sync(FULL, m, 2));
                    if (i == 3) m = fmaxf(m, __shfl_xor_sync(FULL, m, 1));
                }
                int e = (__float_as_int(m) >> 23) & 255;
                int f = 294 - e;                 // exponent field of 2^(167-e)
                if (f > 254) f = 254;
                if (f < 1)   f = 1;
                float sc = __int_as_float(f << 23);   // exact power of 2
                E -= (f - 127);
#pragma unroll
                for (int k = 0; k < 5; k++) a[k] *= sc;
            }
        } else {
            // -------- produce chunk c+1 into buf ((c+1)&1) --------
            int cn = c + 1;
            if (cn < NCH) {
                const int bufn = cn & 1;
                const int tb2  = 1 + cn * CHUNK;
                for (int j = w - 1; j < CHUNK; j += 3) {
                    int t = tb2 + j;
                    if (t < TT) {
                        const float* row = yp + (size_t)t * CC;
                        sp[bufn][j][lane]      = row[labA] + EPSF;
                        sp[bufn][j][lane + 32] = row[labB] + EPSF;
                        if (lane == 0) sp[bufn][j][64] = row[CC - 1] + EPSF;
                    }
                }
            }
        }
        __syncthreads();
    }

    if (w == 0) {
        // loss = -log(alpha[S-1] + alpha[S-2]) with scale restored
        float v127 = __shfl_sync(FULL, a[3], 31);   // state 127 = 32*3 + 31
        float v128 = __shfl_sync(FULL, a[4], 0);    // state 128 = 32*4 + 0
        if (lane == 0)
            out[b] = -(logf(v127 + v128) + (float)E * 0.69314718055994530942f);
    }
}

extern "C" void kernel_launch(void* const* d_in, const int* in_sizes, int n_in,
                              void* d_out, int out_size)
{
    const int*   y_true;
    const float* y_pred;
    if (in_sizes[0] == BB * LL) {
        y_true = (const int*)d_in[0];
        y_pred = (const float*)d_in[1];
    } else {
        y_true = (const int*)d_in[1];
        y_pred = (const float*)d_in[0];
    }
    float* out = (float*)d_out;

    ctc_scaled_kernel<<<BB, 128>>>(y_true, y_pred, out);
}

// round 4
// speedup vs baseline: 1.3490x; 1.3490x over previous
#include <cuda_runtime.h>
#include <cstdint>

// CTC loss (scaled forward algorithm, linear domain).
// B=512, T=512, C=256, L=64, S=129, blank = C-1.
// One warp per batch. Probabilities streamed as FULL raw rows via
// cp.async.bulk (TMA path, no LSU issue cost) into a 2-stage smem ring of
// 16 timesteps each; the warp gathers 5 values/step from smem with LDS.

#define TT 512
#define CC 256
#define BB 512
#define LL 64
#define SS 129
#define EPSF 1e-7f
#define RPC 16                 // rows (timesteps) per chunk
#define NCH 32                 // chunks covering t = 1 .. 511

__device__ __forceinline__ uint32_t smem_u32(const void* p) {
    uint32_t a;
    asm("{ .reg .u64 t; cvta.to.shared.u64 t, %1; cvt.u32.u64 %0, t; }"
        : "=r"(a) : "l"(p));
    return a;
}

__device__ __forceinline__ void mbar_init(uint32_t addr, uint32_t cnt) {
    asm volatile("mbarrier.init.shared.b64 [%0], %1;" :: "r"(addr), "r"(cnt) : "memory");
}
__device__ __forceinline__ void mbar_expect_tx(uint32_t addr, uint32_t bytes) {
    asm volatile("mbarrier.arrive.expect_tx.shared.b64 _, [%0], %1;"
                 :: "r"(addr), "r"(bytes) : "memory");
}
__device__ __forceinline__ void mbar_wait(uint32_t addr, uint32_t parity) {
    asm volatile(
        "{\n\t.reg .pred P;\n\t"
        "LAB_WAIT_%=:\n\t"
        "mbarrier.try_wait.parity.acquire.cta.shared::cta.b64 P, [%0], %1, 0x989680;\n\t"
        "@P bra.uni LAB_DONE_%=;\n\t"
        "bra.uni LAB_WAIT_%=;\n\t"
        "LAB_DONE_%=:\n\t}"
        :: "r"(addr), "r"(parity) : "memory");
}
__device__ __forceinline__ void bulk_copy(uint32_t dst, const void* src,
                                          uint32_t bytes, uint32_t mbar) {
    asm volatile(
        "cp.async.bulk.shared::cluster.global.mbarrier::complete_tx::bytes "
        "[%0], [%1], %2, [%3];"
        :: "r"(dst), "l"(src), "r"(bytes), "r"(mbar) : "memory");
}

__global__ __launch_bounds__(32, 6)
void ctc_tma_kernel(const int* __restrict__ y_true,
                    const float* __restrict__ y_pred,
                    float* __restrict__ out)
{
    __shared__ __align__(16) float sp[2][RPC][CC];
    __shared__ __align__(8)  unsigned long long mbar_s[2];

    const int b    = blockIdx.x;
    const int lane = threadIdx.x;
    const unsigned FULL = 0xFFFFFFFFu;

    const float* __restrict__ yp  = y_pred + (size_t)b * TT * CC;
    const int*   __restrict__ lab = y_true + b * LL;

    const uint32_t mb[2]  = { smem_u32(&mbar_s[0]), smem_u32(&mbar_s[1]) };
    const uint32_t spa[2] = { smem_u32(&sp[0][0][0]), smem_u32(&sp[1][0][0]) };
    (void)spa;

    // ---- static state metadata: s = 32k + lane ----
    int   off[5];
    float skipf[5];
#pragma unroll
    for (int k = 0; k < 5; k++) {
        int s = 32 * k + lane;
        if (s < SS && (s & 1)) {
            int idx = (s - 1) >> 1;
            int cl  = lab[idx];
            off[k]  = cl;
            skipf[k] = (idx > 0 && cl != lab[idx - 1]) ? 1.0f : 0.0f;
        } else {
            off[k]  = CC - 1;     // blank (safe dummy for invalid s > 128)
            skipf[k] = 0.0f;
        }
    }

    // ---- t = 0 init ----
    float a[5];
#pragma unroll
    for (int k = 0; k < 5; k++) a[k] = 0.0f;
    if (lane == 0)      a[0] = yp[CC - 1]  + EPSF;
    else if (lane == 1) a[0] = yp[lab[0]]  + EPSF;

    // ---- pipeline prologue: init barriers, launch chunks 0 and 1 ----
    if (lane == 0) {
        mbar_init(mb[0], 1);
        mbar_init(mb[1], 1);
        asm volatile("fence.proxy.async.shared::cta;" ::: "memory");
#pragma unroll
        for (int c0 = 0; c0 < 2; c0++) {
            int t0   = 1 + RPC * c0;
            int rows = (TT - t0 < RPC) ? (TT - t0) : RPC;
            uint32_t bytes = (uint32_t)rows * CC * 4;
            mbar_expect_tx(mb[c0], bytes);
            bulk_copy(smem_u32(&sp[c0][0][0]), yp + (size_t)t0 * CC, bytes, mb[c0]);
        }
    }
    __syncwarp();

    int E = 0;
    int ph[2] = {0, 0};
    const int lm1 = (lane + 31) & 31;
    const int lm2 = (lane + 30) & 31;

#pragma unroll 1
    for (int c = 0; c < NCH; c++) {
        const int buf   = c & 1;
        const int tbase = 1 + RPC * c;

        mbar_wait(mb[buf], ph[buf]);
        ph[buf] ^= 1;

        // first-row prob prefetch
        float p[5];
        {
            const float* r0 = &sp[buf][0][0];
#pragma unroll
            for (int k = 0; k < 5; k++) p[k] = r0[off[k]] + EPSF;
        }

#pragma unroll 1
        for (int g = 0; g < RPC / 4; g++) {
            // max measured at group start (lagged 1 group), butterfly
            // interleaved with the steps; exact pow-2 scale applied at group
            // end, target biased to 2^40 to keep range above FTZ.
            float m = fmaxf(fmaxf(fmaxf(a[0], a[1]), fmaxf(a[2], a[3])), a[4]);
            m = fmaxf(m, __shfl_xor_sync(FULL, m, 16));

#pragma unroll
            for (int i = 0; i < 4; i++) {
                int j = g * 4 + i;
                int t = tbase + j;
                if (t < TT) {
                    bool pf = (j + 1 < RPC) && (t + 1 < TT);
                    float np[5];
                    const float* rn = &sp[buf][j + 1][0];
                    if (pf) {
#pragma unroll
                        for (int k = 0; k < 5; k++) np[k] = rn[off[k]] + EPSF;
                    }
                    float r1[5], r2[5];
#pragma unroll
                    for (int k = 0; k < 5; k++) r1[k] = __shfl_sync(FULL, a[k], lm1);
#pragma unroll
                    for (int k = 0; k < 5; k++) r2[k] = __shfl_sync(FULL, a[k], lm2);
#pragma unroll
                    for (int k = 0; k < 5; k++) {
                        float u1 = r1[k];
                        if (lane == 0) u1 = (k > 0) ? r1[k - 1] : 0.0f;
                        float u2 = r2[k];
                        if (lane < 2)  u2 = (k > 0) ? r2[k - 1] : 0.0f;
                        float sum = a[k] + u1 + skipf[k] * u2;
                        a[k] = sum * p[k];
                        if (pf) p[k] = np[k];
                    }
                }
                if (i == 0) m = fmaxf(m, __shfl_xor_sync(FULL, m, 8));
                if (i == 1) m = fmaxf(m, __shfl_xor_sync(FULL, m, 4));
                if (i == 2) m = fmaxf(m, __shfl_xor_sync(FULL, m, 2));
                if (i == 3) m = fmaxf(m, __shfl_xor_sync(FULL, m, 1));
            }
            int e = (__float_as_int(m) >> 23) & 255;
            int f = 294 - e;                    // exponent field of 2^(167-e)
            if (f > 254) f = 254;
            if (f < 1)   f = 1;
            float sc = __int_as_float(f << 23); // exact power of 2
            E -= (f - 127);
#pragma unroll
            for (int k = 0; k < 5; k++) a[k] *= sc;
        }

        // buffer fully drained by all lanes -> refill it with chunk c+2
        __syncwarp();
        int cn = c + 2;
        if (cn < NCH && lane == 0) {
            int t0   = 1 + RPC * cn;
            int rows = (TT - t0 < RPC) ? (TT - t0) : RPC;
            uint32_t bytes = (uint32_t)rows * CC * 4;
            mbar_expect_tx(mb[buf], bytes);
            bulk_copy(smem_u32(&sp[buf][0][0]), yp + (size_t)t0 * CC, bytes, mb[buf]);
        }
    }

    // ---- loss = -log(alpha[S-1] + alpha[S-2]), scale restored ----
    float v127 = __shfl_sync(FULL, a[3], 31);   // state 127 = 32*3 + 31
    float v128 = __shfl_sync(FULL, a[4], 0);    // state 128 = 32*4 + 0
    if (lane == 0)
        out[b] = -(logf(v127 + v128) + (float)E * 0.69314718055994530942f);
}

extern "C" void kernel_launch(void* const* d_in, const int* in_sizes, int n_in,
                              void* d_out, int out_size)
{
    const int*   y_true;
    const float* y_pred;
    if (in_sizes[0] == BB * LL) {
        y_true = (const int*)d_in[0];
        y_pred = (const float*)d_in[1];
    } else {
        y_true = (const int*)d_in[1];
        y_pred = (const float*)d_in[0];
    }
    float* out = (float*)d_out;

    ctc_tma_kernel<<<BB, 32>>>(y_true, y_pred, out);
}